// round 13
// baseline (speedup 1.0000x reference)
#include <cuda_runtime.h>
#include <cuda_bf16.h>
#include <cuda_fp16.h>
#include <math.h>

#define BB 32
#define SS 50
#define TD 49
#define EE 128
#define HH 128
#define GG 512
#define VV 32000

typedef unsigned long long u64;
typedef unsigned int u32;

// ---------------- device scratch (no allocations allowed) --------------------
__device__ float g_encPre[SS * BB * GG];
__device__ float g_decPre[TD * BB * GG];
__device__ float g_encOut[BB * SS * HH];
__device__ float g_attSrc[BB * SS * HH];
__device__ float g_decH[TD * BB * HH];
__device__ unsigned short g_Ahi[1568 * 128];   // finals, fp16
__device__ unsigned short g_Bhi[VV * 128];     // sm_w, fp16

// ---------------- helpers ----------------------------------------------------
__device__ __forceinline__ float sigm(float x) {
    return 1.0f / (1.0f + __expf(-x));
}
__device__ __forceinline__ float ftanh(float x) {
    float e = __expf(-2.0f * fabsf(x));
    float r = __fdividef(1.0f - e, 1.0f + e);
    return copysignf(r, x);
}
__device__ __forceinline__ float htanh(float x) {   // HW MUFU.TANH
    float y;
    asm("tanh.approx.f32 %0, %1;" : "=f"(y) : "f"(x));
    return y;
}
__device__ __forceinline__ u32 smem_u32(const void* p) {
    u32 a;
    asm("{ .reg .u64 t; cvta.to.shared.u64 t, %1; cvt.u32.u64 %0, t; }" : "=r"(a) : "l"(p));
    return a;
}
__device__ __forceinline__ void ldsm4(u32* r, u32 addr) {
    asm volatile("ldmatrix.sync.aligned.m8n8.x4.shared.b16 {%0,%1,%2,%3}, [%4];"
                 : "=r"(r[0]), "=r"(r[1]), "=r"(r[2]), "=r"(r[3]) : "r"(addr));
}
__device__ __forceinline__ void mma16816(float* c, const u32* a, u32 b0, u32 b1) {
    asm volatile(
        "mma.sync.aligned.m16n8k16.row.col.f32.f16.f16.f32 "
        "{%0,%1,%2,%3}, {%4,%5,%6,%7}, {%8,%9}, {%0,%1,%2,%3};"
        : "+f"(c[0]), "+f"(c[1]), "+f"(c[2]), "+f"(c[3])
        : "r"(a[0]), "r"(a[1]), "r"(a[2]), "r"(a[3]), "r"(b0), "r"(b1));
}

// ---------------- K1: precompute x @ Wih^T + bih + bhh (enc + dec merged) ----
__global__ void pre_kernel(const int* __restrict__ srcTok,
                           const int* __restrict__ trgTok,
                           const float* __restrict__ embS,
                           const float* __restrict__ embT,
                           const float* __restrict__ eWih,
                           const float* __restrict__ ebih,
                           const float* __restrict__ ebhh,
                           const float* __restrict__ dWih,
                           const float* __restrict__ dbih,
                           const float* __restrict__ dbhh)
{
    int bid = blockIdx.x;
    int which = (bid >= 200);
    const int*   tok = which ? trgTok : srcTok;
    const float* emb = which ? embT   : embS;
    const float* Wih = which ? dWih   : eWih;
    const float* bih = which ? dbih   : ebih;
    const float* bhh = which ? dbhh   : ebhh;
    float* outp      = which ? g_decPre : g_encPre;
    int Tlen         = which ? TD : SS;
    int p0 = (which ? bid - 200 : bid) * 8;

    __shared__ float es[8][128];
    int tid = threadIdx.x;
    int total = Tlen * BB;
    for (int idx = tid; idx < 8 * 128; idx += 256) {
        int pi = idx >> 7, kk = idx & 127;
        int p = p0 + pi;
        float v = 0.0f;
        if (p < total) {
            int t = p >> 5, b = p & 31;
            int tv = tok[b * SS + t];
            v = emb[(size_t)tv * EE + kk];
        }
        es[pi][kk] = v;
    }
    __syncthreads();
    int j0 = tid, j1 = tid + 256;
    float acc0[8], acc1[8];
    float bi0 = bih[j0] + bhh[j0];
    float bi1 = bih[j1] + bhh[j1];
#pragma unroll
    for (int pi = 0; pi < 8; pi++) { acc0[pi] = bi0; acc1[pi] = bi1; }
    const float4* w0 = (const float4*)(Wih + (size_t)j0 * EE);
    const float4* w1 = (const float4*)(Wih + (size_t)j1 * EE);
    for (int q = 0; q < 32; q++) {
        float4 a = w0[q];
        float4 c = w1[q];
#pragma unroll
        for (int pi = 0; pi < 8; pi++) {
            float4 e = *(const float4*)&es[pi][q * 4];
            acc0[pi] += a.x * e.x + a.y * e.y + a.z * e.z + a.w * e.w;
            acc1[pi] += c.x * e.x + c.y * e.y + c.z * e.z + c.w * e.w;
        }
    }
    for (int pi = 0; pi < 8; pi++) {
        int p = p0 + pi;
        if (p < total) {
            outp[(size_t)p * GG + j0] = acc0[pi];
            outp[(size_t)p * GG + j1] = acc1[pi];
        }
    }
}

// ---------------- K2: merged LSTM recurrences + fused att_src ----------------
#define LSTM_SMEM ((64 * 512 + 50 * 128 + 128 + 128 + 512) * 4)

__global__ __launch_bounds__(512, 1)
void lstm_kernel(const float* __restrict__ eWhh,
                 const float* __restrict__ dWhh,
                 const float* __restrict__ w1s,
                 const float* __restrict__ b1s)
{
    extern __shared__ float sm[];
    float* sW   = sm;                       // [64 k][512 j]
    float* hist = sm + 64 * 512;            // [50][128]
    float* hs   = hist + 50 * 128;
    float* cs   = hs + 128;
    float* gbuf = cs + 128;

    int bid = blockIdx.x;
    int which = (bid >= 32);
    int b = bid & 31;
    const float* Whh = which ? dWhh : eWhh;
    const float* pre = which ? g_decPre : g_encPre;
    int steps = which ? TD : SS;
    int tid = threadIdx.x, j = tid;

    float4 wr[16];
    const float4* wrow = (const float4*)(Whh + (size_t)j * 128);
#pragma unroll
    for (int q = 0; q < 16; q++) wr[q] = wrow[q];
    for (int idx = tid; idx < 64 * 512; idx += 512) {
        int k2 = idx >> 9, jj = idx & 511;
        sW[idx] = Whh[(size_t)jj * 128 + 64 + k2];
    }
    if (tid < 128) { hs[tid] = 0.0f; cs[tid] = 0.0f; }
    __syncthreads();

    const float* preB = pre + (size_t)b * GG;
    float cur = preB[j];
    for (int t = 0; t < steps; t++) {
        float acc = cur;
        const float4* h4 = (const float4*)hs;
#pragma unroll
        for (int q = 0; q < 16; q++) {
            float4 hv = h4[q];
            acc += wr[q].x * hv.x + wr[q].y * hv.y + wr[q].z * hv.z + wr[q].w * hv.w;
        }
#pragma unroll
        for (int c = 16; c < 32; c++) {
            float4 hv = h4[c];
            int k2 = (c - 16) * 4;
            acc += sW[(k2 + 0) * 512 + j] * hv.x + sW[(k2 + 1) * 512 + j] * hv.y
                 + sW[(k2 + 2) * 512 + j] * hv.z + sW[(k2 + 3) * 512 + j] * hv.w;
        }
        gbuf[j] = acc;
        __syncthreads();
        if (t + 1 < steps) cur = preB[(size_t)(t + 1) * BB * GG + j];
        if (tid < 128) {
            float ig = gbuf[tid], fg = gbuf[128 + tid];
            float gg = gbuf[256 + tid], og = gbuf[384 + tid];
            float cc = sigm(fg) * cs[tid] + sigm(ig) * ftanh(gg);
            float hv = sigm(og) * ftanh(cc);
            cs[tid] = cc;
            hs[tid] = hv;
            if (which) {
                g_decH[(size_t)(t * 32 + b) * 128 + tid] = hv;
            } else {
                hist[t * 128 + tid] = hv;
                g_encOut[(size_t)(b * 50 + t) * 128 + tid] = hv;
            }
        }
        __syncthreads();
    }

    // fused att_src (encoder CTAs)
    if (!which) {
        int a = tid & 127;
        int sB = tid >> 7;
        const float* hp[13];
#pragma unroll
        for (int q = 0; q < 13; q++) {
            int s = sB + 4 * q;
            hp[q] = hist + (s < 50 ? s : 49) * 128;
        }
        float accv[13];
#pragma unroll
        for (int q = 0; q < 13; q++) accv[q] = 0.0f;
        const float* wrowa = w1s + (size_t)a * 128;
        for (int k = 0; k < 128; k++) {
            float w = __ldg(wrowa + k);
#pragma unroll
            for (int q = 0; q < 13; q++) accv[q] += hp[q][k] * w;
        }
        float bv = b1s[a];
#pragma unroll
        for (int q = 0; q < 13; q++) {
            int s = sB + 4 * q;
            if (s < 50) g_attSrc[(size_t)(b * 50 + s) * 128 + a] = accv[q] + bv;
        }
    }
}

// ---------------- K3: batched attention + final (7 t's per CTA) --------------
// grid (32 b, 7 tg), 256 threads. asrc[b], enc_out[b] staged in smem once.
#define AT_ASRC 0
#define AT_EO   6400
#define AT_HS   12800
#define AT_ATG  13696
#define AT_AVS  14592
#define AT_SC   15488
#define AT_AL   15852
#define ATTN_SMEM (16216 * 4)

__global__ __launch_bounds__(256, 3)
void attn_kernel(const float* __restrict__ w1t,
                 const float* __restrict__ b1t,
                 const float* __restrict__ w2,
                 const float* __restrict__ b2,
                 const float* __restrict__ out_w,
                 const float* __restrict__ out_b)
{
    extern __shared__ float sb[];
    float* asrc = sb + AT_ASRC;
    float* eo   = sb + AT_EO;
    float* hsm  = sb + AT_HS;    // [7][128]
    float* atg  = sb + AT_ATG;   // [7][128]
    float* avs  = sb + AT_AVS;   // [7][128]
    float* sc   = sb + AT_SC;    // [7][52]
    float* al   = sb + AT_AL;    // [7][52]

    int b = blockIdx.x;
    int t0 = blockIdx.y * 7;
    int tid = threadIdx.x;

    {
        const float4* ga = (const float4*)(g_attSrc + (size_t)(b * 50) * 128);
        const float4* ge = (const float4*)(g_encOut + (size_t)(b * 50) * 128);
        for (int i = tid; i < 1600; i += 256) {
            ((float4*)asrc)[i] = ga[i];
            ((float4*)eo)[i]   = ge[i];
        }
        for (int i = tid; i < 7 * 128; i += 256) {
            int r = i >> 7, k = i & 127;
            hsm[i] = g_decH[(size_t)((t0 + r) * 32 + b) * 128 + k];
        }
    }
    __syncthreads();

    int lane128 = tid & 127;
    int rset = tid >> 7;

    // P2: att_tgt
    {
        int a = lane128;
        float acc[4] = {0.f, 0.f, 0.f, 0.f};
        const float4* w4 = (const float4*)(w1t + (size_t)a * 128);
        for (int q = 0; q < 32; q++) {
            float4 w = w4[q];
#pragma unroll
            for (int u = 0; u < 4; u++) {
                int r = rset + 2 * u;
                if (r < 7) {
                    float4 h = *(const float4*)&hsm[r * 128 + q * 4];
                    acc[u] += w.x * h.x + w.y * h.y + w.z * h.z + w.w * h.w;
                }
            }
        }
        float bv = b1t[a];
#pragma unroll
        for (int u = 0; u < 4; u++) {
            int r = rset + 2 * u;
            if (r < 7) atg[r * 128 + a] = acc[u] + bv;
        }
    }
    __syncthreads();

    // P3: scores
    {
        int w = tid >> 5, l = tid & 31;
        float4 wv = __ldg((const float4*)w2 + l);
        float b2v = b2[0];
        for (int task = w; task < 350; task += 8) {
            int r = task / 50, s = task - r * 50;
            float4 av = *(const float4*)&asrc[s * 128 + l * 4];
            float4 tg = *(const float4*)&atg[r * 128 + l * 4];
            float p = htanh(av.x + tg.x) * wv.x + htanh(av.y + tg.y) * wv.y
                    + htanh(av.z + tg.z) * wv.z + htanh(av.w + tg.w) * wv.w;
#pragma unroll
            for (int o = 16; o; o >>= 1) p += __shfl_down_sync(0xffffffffu, p, o);
            if (l == 0) sc[r * 52 + s] = p + b2v;
        }
    }
    __syncthreads();

    // P4: softmax
    {
        int w = tid >> 5, l = tid & 31;
        if (w < 7) {
            float v0 = (l < 50) ? sc[w * 52 + l] : -1e30f;
            float v1 = (l + 32 < 50) ? sc[w * 52 + l + 32] : -1e30f;
            float mx = fmaxf(v0, v1);
#pragma unroll
            for (int o = 16; o; o >>= 1) mx = fmaxf(mx, __shfl_xor_sync(0xffffffffu, mx, o));
            float e0 = (l < 50) ? __expf(v0 - mx) : 0.0f;
            float e1 = (l + 32 < 50) ? __expf(v1 - mx) : 0.0f;
            float sum = e0 + e1;
#pragma unroll
            for (int o = 16; o; o >>= 1) sum += __shfl_xor_sync(0xffffffffu, sum, o);
            float inv = __fdividef(1.0f, sum);
            if (l < 50) al[w * 52 + l] = e0 * inv;
            if (l + 32 < 50) al[w * 52 + l + 32] = e1 * inv;
        }
    }
    __syncthreads();

    // P5: att_vec
    {
        int h = lane128;
        float acc[4] = {0.f, 0.f, 0.f, 0.f};
        for (int s = 0; s < 50; s++) {
            float ev = eo[s * 128 + h];
#pragma unroll
            for (int u = 0; u < 4; u++) {
                int r = rset + 2 * u;
                if (r < 7) acc[u] += al[r * 52 + s] * ev;
            }
        }
#pragma unroll
        for (int u = 0; u < 4; u++) {
            int r = rset + 2 * u;
            if (r < 7) avs[r * 128 + h] = acc[u];
        }
    }
    __syncthreads();

    // P6: final -> fp16
    {
        int j = lane128;
        float acc[4] = {0.f, 0.f, 0.f, 0.f};
        const float4* w4 = (const float4*)(out_w + (size_t)j * 256);
        for (int q = 0; q < 32; q++) {
            float4 w0 = w4[q];
            float4 w1 = w4[32 + q];
#pragma unroll
            for (int u = 0; u < 4; u++) {
                int r = rset + 2 * u;
                if (r < 7) {
                    float4 h = *(const float4*)&hsm[r * 128 + q * 4];
                    float4 a = *(const float4*)&avs[r * 128 + q * 4];
                    acc[u] += w0.x * h.x + w0.y * h.y + w0.z * h.z + w0.w * h.w
                            + w1.x * a.x + w1.y * a.y + w1.z * a.z + w1.w * a.w;
                }
            }
        }
        float bv = out_b[j];
#pragma unroll
        for (int u = 0; u < 4; u++) {
            int r = rset + 2 * u;
            if (r < 7) {
                float fv = ftanh(acc[u] + bv);
                size_t m = (size_t)((t0 + r) * 32 + b) * 128 + j;
                g_Ahi[m] = __half_as_ushort(__float2half_rn(fv));
            }
        }
    }
}

// ---------------- K4: convert sm_w fp32 -> fp16 ------------------------------
__global__ void convB_kernel(const float* __restrict__ w)
{
    int idx = blockIdx.x * 256 + threadIdx.x;   // float4 index
    const int total = VV * 128 / 4;
    for (int i = idx; i < total; i += gridDim.x * 256) {
        float4 v = __ldg((const float4*)w + i);
        ushort4 hv = make_ushort4(
            __half_as_ushort(__float2half_rn(v.x)),
            __half_as_ushort(__float2half_rn(v.y)),
            __half_as_ushort(__float2half_rn(v.z)),
            __half_as_ushort(__float2half_rn(v.w)));
        ((ushort4*)g_Bhi)[i] = hv;
    }
}

// ---------------- K5: fp16 mma.sync single-pass GEMM -------------------------
// D[1568,32000] = A@B^T + bias. CTA tile M=64 x N=128, K=128 smem-resident.
// launch_bounds(256,2): ~128-reg budget, NO spills (the R12 (256,3) regression).
#define GSTR 272
#define OFF_A 0
#define OFF_B (64 * GSTR)                  // 17408
#define GEMM_SMEM (OFF_B + 128 * GSTR)     // 52224 B

__global__ __launch_bounds__(256, 2)
void gemm_kernel(const float* __restrict__ smb, float* __restrict__ outp)
{
    extern __shared__ char smc[];
    u32 sbse = smem_u32(smc);
    int tid = threadIdx.x;
    int n0 = blockIdx.x * 128;
    int m0 = blockIdx.y * 64;

    for (int idx = tid; idx < 64 * 16; idx += 256) {         // A
        int r = idx >> 4, c = idx & 15;
        int m = m0 + r;
        uint4 v = make_uint4(0, 0, 0, 0);
        if (m < 1568) v = ((const uint4*)g_Ahi)[m * 16 + c];
        *(uint4*)(smc + OFF_A + r * GSTR + c * 16) = v;
    }
    for (int idx = tid; idx < 128 * 16; idx += 256) {        // B
        int r = idx >> 4, c = idx & 15;
        int n = n0 + r;
        *(uint4*)(smc + OFF_B + r * GSTR + c * 16) = ((const uint4*)g_Bhi)[n * 16 + c];
    }
    __syncthreads();

    int wid = tid >> 5, l = tid & 31;
    int wm = (wid >> 2) * 32;
    int wn = (wid & 3) * 32;

    u32 aoff = (u32)((wm + (l & 15)) * GSTR + ((l >> 4) << 4));
    u32 boff = (u32)((wn + ((l >> 4) << 3) + (l & 7)) * GSTR + (((l >> 3) & 1) << 4));
    u32 aAddr = sbse + OFF_A + aoff;
    u32 bAddr = sbse + OFF_B + boff;

    float c[2][4][4];
#pragma unroll
    for (int i = 0; i < 2; i++)
#pragma unroll
        for (int j = 0; j < 4; j++)
#pragma unroll
            for (int q = 0; q < 4; q++) c[i][j][q] = 0.0f;

#pragma unroll
    for (int ks = 0; ks < 8; ks++) {
        u32 a0[4], a1[4], b0[4], b1[4];
        ldsm4(a0, aAddr + ks * 32);
        ldsm4(a1, aAddr + 16 * GSTR + ks * 32);
        ldsm4(b0, bAddr + ks * 32);
        ldsm4(b1, bAddr + 16 * GSTR + ks * 32);
        mma16816(c[0][0], a0, b0[0], b0[1]);
        mma16816(c[0][1], a0, b0[2], b0[3]);
        mma16816(c[0][2], a0, b1[0], b1[1]);
        mma16816(c[0][3], a0, b1[2], b1[3]);
        mma16816(c[1][0], a1, b0[0], b0[1]);
        mma16816(c[1][1], a1, b0[2], b0[3]);
        mma16816(c[1][2], a1, b1[0], b1[1]);
        mma16816(c[1][3], a1, b1[2], b1[3]);
    }

#pragma unroll
    for (int nf = 0; nf < 4; nf++) {
        int cb = n0 + wn + nf * 8 + 2 * (l & 3);
        float2 bv = __ldg((const float2*)(smb + cb));
#pragma unroll
        for (int mf = 0; mf < 2; mf++) {
            int mrow = m0 + wm + mf * 16 + (l >> 2);
#pragma unroll
            for (int h = 0; h < 2; h++) {
                int m = mrow + h * 8;
                if (m < 1568) {
                    int t = m >> 5, b = m & 31;
                    float2 o;
                    o.x = c[mf][nf][h * 2 + 0] + bv.x;
                    o.y = c[mf][nf][h * 2 + 1] + bv.y;
                    *(float2*)(outp + (size_t)(b * 49 + t) * 32000 + cb) = o;
                }
            }
        }
    }
}

extern "C" void kernel_launch(void* const* d_in, const int* in_sizes, int n_in,
                              void* d_out, int out_size)
{
    const int*   src     = (const int*)  d_in[0];
    const int*   trg     = (const int*)  d_in[1];
    const float* emb_src = (const float*)d_in[2];
    const float* emb_trg = (const float*)d_in[3];
    const float* enc_Wih = (const float*)d_in[4];
    const float* enc_Whh = (const float*)d_in[5];
    const float* enc_bih = (const float*)d_in[6];
    const float* enc_bhh = (const float*)d_in[7];
    const float* dec_Wih = (const float*)d_in[8];
    const float* dec_Whh = (const float*)d_in[9];
    const float* dec_bih = (const float*)d_in[10];
    const float* dec_bhh = (const float*)d_in[11];
    const float* att_w1s = (const float*)d_in[12];
    const float* att_b1s = (const float*)d_in[13];
    const float* att_w1t = (const float*)d_in[14];
    const float* att_b1t = (const float*)d_in[15];
    const float* att_w2  = (const float*)d_in[16];
    const float* att_b2  = (const float*)d_in[17];
    const float* out_w   = (const float*)d_in[18];
    const float* out_b   = (const float*)d_in[19];
    const float* sm_w    = (const float*)d_in[20];
    const float* sm_b    = (const float*)d_in[21];
    float* outp = (float*)d_out;

    cudaFuncSetAttribute(lstm_kernel,
                         cudaFuncAttributeMaxDynamicSharedMemorySize, LSTM_SMEM);
    cudaFuncSetAttribute(attn_kernel,
                         cudaFuncAttributeMaxDynamicSharedMemorySize, ATTN_SMEM);
    cudaFuncSetAttribute(gemm_kernel,
                         cudaFuncAttributeMaxDynamicSharedMemorySize, GEMM_SMEM);

    pre_kernel<<<396, 256>>>(src, trg, emb_src, emb_trg,
                             enc_Wih, enc_bih, enc_bhh,
                             dec_Wih, dec_bih, dec_bhh);
    convB_kernel<<<1000, 256>>>(sm_w);
    lstm_kernel<<<64, 512, LSTM_SMEM>>>(enc_Whh, dec_Whh, att_w1s, att_b1s);
    attn_kernel<<<dim3(32, 7), 256, ATTN_SMEM>>>(att_w1t, att_b1t, att_w2,
                                                 att_b2, out_w, out_b);
    gemm_kernel<<<dim3(250, 25), 256, GEMM_SMEM>>>(sm_b, outp);
}

// round 14
// speedup vs baseline: 1.1232x; 1.1232x over previous
#include <cuda_runtime.h>
#include <cuda_bf16.h>
#include <cuda_fp16.h>
#include <math.h>

#define BB 32
#define SS 50
#define TD 49
#define EE 128
#define HH 128
#define GG 512
#define VV 32000

typedef unsigned long long u64;
typedef unsigned int u32;

// ---------------- device scratch (no allocations allowed) --------------------
__device__ float g_encPre[SS * BB * GG];
__device__ float g_decPre[TD * BB * GG];
__device__ float g_encOut[BB * SS * HH];
__device__ float g_attSrc[BB * SS * HH];
__device__ float g_decH[TD * BB * HH];
__device__ float g_w1tT[128 * 128];            // w1t transposed [k][a]
__device__ float g_outwT[256 * 128];           // out_w transposed [k][j]
__device__ float g_w1sT[128 * 128];            // w1s transposed [k][a]
__device__ unsigned short g_Ahi[1568 * 128];   // finals, fp16
__device__ unsigned short g_Bhi[VV * 128];     // sm_w, fp16

// ---------------- helpers ----------------------------------------------------
__device__ __forceinline__ float sigm(float x) {
    return 1.0f / (1.0f + __expf(-x));
}
__device__ __forceinline__ float ftanh(float x) {
    float e = __expf(-2.0f * fabsf(x));
    float r = __fdividef(1.0f - e, 1.0f + e);
    return copysignf(r, x);
}
__device__ __forceinline__ float htanh(float x) {   // HW MUFU.TANH
    float y;
    asm("tanh.approx.f32 %0, %1;" : "=f"(y) : "f"(x));
    return y;
}
__device__ __forceinline__ u32 smem_u32(const void* p) {
    u32 a;
    asm("{ .reg .u64 t; cvta.to.shared.u64 t, %1; cvt.u32.u64 %0, t; }" : "=r"(a) : "l"(p));
    return a;
}
__device__ __forceinline__ void ldsm4(u32* r, u32 addr) {
    asm volatile("ldmatrix.sync.aligned.m8n8.x4.shared.b16 {%0,%1,%2,%3}, [%4];"
                 : "=r"(r[0]), "=r"(r[1]), "=r"(r[2]), "=r"(r[3]) : "r"(addr));
}
__device__ __forceinline__ void mma16816(float* c, const u32* a, u32 b0, u32 b1) {
    asm volatile(
        "mma.sync.aligned.m16n8k16.row.col.f32.f16.f16.f32 "
        "{%0,%1,%2,%3}, {%4,%5,%6,%7}, {%8,%9}, {%0,%1,%2,%3};"
        : "+f"(c[0]), "+f"(c[1]), "+f"(c[2]), "+f"(c[3])
        : "r"(a[0]), "r"(a[1]), "r"(a[2]), "r"(a[3]), "r"(b0), "r"(b1));
}

// ---------------- K0: transpose small weights to k-major ---------------------
// 65536 threads total: w1tT 16384 | outwT 32768 | w1sT 16384
__global__ void prep_kernel(const float* __restrict__ w1t,
                            const float* __restrict__ out_w,
                            const float* __restrict__ w1s)
{
    int i = blockIdx.x * 256 + threadIdx.x;
    if (i < 16384) {
        int k = i >> 7, a = i & 127;
        g_w1tT[i] = w1t[a * 128 + k];
    } else if (i < 49152) {
        int i2 = i - 16384;
        int k = i2 >> 7, j = i2 & 127;
        g_outwT[i2] = out_w[j * 256 + k];
    } else {
        int i2 = i - 49152;
        int k = i2 >> 7, a = i2 & 127;
        g_w1sT[i2] = w1s[a * 128 + k];
    }
}

// ---------------- K1: precompute x @ Wih^T + bih + bhh (enc + dec merged) ----
__global__ void pre_kernel(const int* __restrict__ srcTok,
                           const int* __restrict__ trgTok,
                           const float* __restrict__ embS,
                           const float* __restrict__ embT,
                           const float* __restrict__ eWih,
                           const float* __restrict__ ebih,
                           const float* __restrict__ ebhh,
                           const float* __restrict__ dWih,
                           const float* __restrict__ dbih,
                           const float* __restrict__ dbhh)
{
    int bid = blockIdx.x;
    int which = (bid >= 200);
    const int*   tok = which ? trgTok : srcTok;
    const float* emb = which ? embT   : embS;
    const float* Wih = which ? dWih   : eWih;
    const float* bih = which ? dbih   : ebih;
    const float* bhh = which ? dbhh   : ebhh;
    float* outp      = which ? g_decPre : g_encPre;
    int Tlen         = which ? TD : SS;
    int p0 = (which ? bid - 200 : bid) * 8;

    __shared__ float es[8][128];
    int tid = threadIdx.x;
    int total = Tlen * BB;
    for (int idx = tid; idx < 8 * 128; idx += 256) {
        int pi = idx >> 7, kk = idx & 127;
        int p = p0 + pi;
        float v = 0.0f;
        if (p < total) {
            int t = p >> 5, b = p & 31;
            int tv = tok[b * SS + t];
            v = emb[(size_t)tv * EE + kk];
        }
        es[pi][kk] = v;
    }
    __syncthreads();
    int j0 = tid, j1 = tid + 256;
    float acc0[8], acc1[8];
    float bi0 = bih[j0] + bhh[j0];
    float bi1 = bih[j1] + bhh[j1];
#pragma unroll
    for (int pi = 0; pi < 8; pi++) { acc0[pi] = bi0; acc1[pi] = bi1; }
    const float4* w0 = (const float4*)(Wih + (size_t)j0 * EE);
    const float4* w1 = (const float4*)(Wih + (size_t)j1 * EE);
    for (int q = 0; q < 32; q++) {
        float4 a = w0[q];
        float4 c = w1[q];
#pragma unroll
        for (int pi = 0; pi < 8; pi++) {
            float4 e = *(const float4*)&es[pi][q * 4];
            acc0[pi] += a.x * e.x + a.y * e.y + a.z * e.z + a.w * e.w;
            acc1[pi] += c.x * e.x + c.y * e.y + c.z * e.z + c.w * e.w;
        }
    }
    for (int pi = 0; pi < 8; pi++) {
        int p = p0 + pi;
        if (p < total) {
            outp[(size_t)p * GG + j0] = acc0[pi];
            outp[(size_t)p * GG + j1] = acc1[pi];
        }
    }
}

// ---------------- K2: merged LSTM recurrences + fused att_src ----------------
#define LSTM_SMEM ((64 * 512 + 50 * 128 + 128 + 128 + 512) * 4)

__global__ __launch_bounds__(512, 1)
void lstm_kernel(const float* __restrict__ eWhh,
                 const float* __restrict__ dWhh,
                 const float* __restrict__ b1s)
{
    extern __shared__ float sm[];
    float* sW   = sm;                       // [64 k][512 j]
    float* hist = sm + 64 * 512;            // [50][128]
    float* hs   = hist + 50 * 128;
    float* cs   = hs + 128;
    float* gbuf = cs + 128;

    int bid = blockIdx.x;
    int which = (bid >= 32);
    int b = bid & 31;
    const float* Whh = which ? dWhh : eWhh;
    const float* pre = which ? g_decPre : g_encPre;
    int steps = which ? TD : SS;
    int tid = threadIdx.x, j = tid;

    float4 wr[16];
    const float4* wrow = (const float4*)(Whh + (size_t)j * 128);
#pragma unroll
    for (int q = 0; q < 16; q++) wr[q] = wrow[q];
    for (int idx = tid; idx < 64 * 512; idx += 512) {
        int k2 = idx >> 9, jj = idx & 511;
        sW[idx] = Whh[(size_t)jj * 128 + 64 + k2];
    }
    if (tid < 128) { hs[tid] = 0.0f; cs[tid] = 0.0f; }
    __syncthreads();

    const float* preB = pre + (size_t)b * GG;
    float cur = preB[j];
    for (int t = 0; t < steps; t++) {
        float acc = cur;
        const float4* h4 = (const float4*)hs;
#pragma unroll
        for (int q = 0; q < 16; q++) {
            float4 hv = h4[q];
            acc += wr[q].x * hv.x + wr[q].y * hv.y + wr[q].z * hv.z + wr[q].w * hv.w;
        }
#pragma unroll
        for (int c = 16; c < 32; c++) {
            float4 hv = h4[c];
            int k2 = (c - 16) * 4;
            acc += sW[(k2 + 0) * 512 + j] * hv.x + sW[(k2 + 1) * 512 + j] * hv.y
                 + sW[(k2 + 2) * 512 + j] * hv.z + sW[(k2 + 3) * 512 + j] * hv.w;
        }
        gbuf[j] = acc;
        __syncthreads();
        if (t + 1 < steps) cur = preB[(size_t)(t + 1) * BB * GG + j];
        if (tid < 128) {
            float ig = gbuf[tid], fg = gbuf[128 + tid];
            float gg = gbuf[256 + tid], og = gbuf[384 + tid];
            float cc = sigm(fg) * cs[tid] + sigm(ig) * ftanh(gg);
            float hv = sigm(og) * ftanh(cc);
            cs[tid] = cc;
            hs[tid] = hv;
            if (which) {
                g_decH[(size_t)(t * 32 + b) * 128 + tid] = hv;
            } else {
                hist[t * 128 + tid] = hv;
                g_encOut[(size_t)(b * 50 + t) * 128 + tid] = hv;
            }
        }
        __syncthreads();
    }

    // fused att_src (encoder CTAs), k-major coalesced weight reads
    if (!which) {
        int a = tid & 127;
        int sB = tid >> 7;
        const float* hp[13];
#pragma unroll
        for (int q = 0; q < 13; q++) {
            int s = sB + 4 * q;
            hp[q] = hist + (s < 50 ? s : 49) * 128;
        }
        float accv[13];
#pragma unroll
        for (int q = 0; q < 13; q++) accv[q] = 0.0f;
#pragma unroll 2
        for (int k = 0; k < 128; k++) {
            float w = __ldg(g_w1sT + k * 128 + a);
#pragma unroll
            for (int q = 0; q < 13; q++) accv[q] += hp[q][k] * w;
        }
        float bv = b1s[a];
#pragma unroll
        for (int q = 0; q < 13; q++) {
            int s = sB + 4 * q;
            if (s < 50) g_attSrc[(size_t)(b * 50 + s) * 128 + a] = accv[q] + bv;
        }
    }
}

// ---------------- K3: batched attention + final (7 t's per CTA) --------------
#define AT_ASRC 0
#define AT_EO   6400
#define AT_HS   12800
#define AT_ATG  13696
#define AT_AVS  14592
#define AT_SC   15488
#define AT_AL   15852
#define ATTN_SMEM (16216 * 4)

__global__ __launch_bounds__(256, 3)
void attn_kernel(const float* __restrict__ b1t,
                 const float* __restrict__ w2,
                 const float* __restrict__ b2,
                 const float* __restrict__ out_b)
{
    extern __shared__ float sb[];
    float* asrc = sb + AT_ASRC;
    float* eo   = sb + AT_EO;
    float* hsm  = sb + AT_HS;    // [7][128]
    float* atg  = sb + AT_ATG;   // [7][128]
    float* avs  = sb + AT_AVS;   // [7][128]
    float* sc   = sb + AT_SC;    // [7][52]
    float* al   = sb + AT_AL;    // [7][52]

    int b = blockIdx.x;
    int t0 = blockIdx.y * 7;
    int tid = threadIdx.x;

    {
        const float4* ga = (const float4*)(g_attSrc + (size_t)(b * 50) * 128);
        const float4* ge = (const float4*)(g_encOut + (size_t)(b * 50) * 128);
        for (int i = tid; i < 1600; i += 256) {
            ((float4*)asrc)[i] = ga[i];
            ((float4*)eo)[i]   = ge[i];
        }
        for (int i = tid; i < 7 * 128; i += 256) {
            int r = i >> 7, k = i & 127;
            hsm[i] = g_decH[(size_t)((t0 + r) * 32 + b) * 128 + k];
        }
    }
    __syncthreads();

    int lane128 = tid & 127;
    int rset = tid >> 7;

    // P2: att_tgt, k-major coalesced weight reads
    {
        int a = lane128;
        float acc[4] = {0.f, 0.f, 0.f, 0.f};
#pragma unroll 2
        for (int k = 0; k < 128; k++) {
            float w = __ldg(g_w1tT + k * 128 + a);
#pragma unroll
            for (int u = 0; u < 4; u++) {
                int r = rset + 2 * u;
                if (r < 7) acc[u] += w * hsm[r * 128 + k];
            }
        }
        float bv = b1t[a];
#pragma unroll
        for (int u = 0; u < 4; u++) {
            int r = rset + 2 * u;
            if (r < 7) atg[r * 128 + a] = acc[u] + bv;
        }
    }
    __syncthreads();

    // P3: scores
    {
        int w = tid >> 5, l = tid & 31;
        float4 wv = __ldg((const float4*)w2 + l);
        float b2v = b2[0];
        for (int task = w; task < 350; task += 8) {
            int r = task / 50, s = task - r * 50;
            float4 av = *(const float4*)&asrc[s * 128 + l * 4];
            float4 tg = *(const float4*)&atg[r * 128 + l * 4];
            float p = htanh(av.x + tg.x) * wv.x + htanh(av.y + tg.y) * wv.y
                    + htanh(av.z + tg.z) * wv.z + htanh(av.w + tg.w) * wv.w;
#pragma unroll
            for (int o = 16; o; o >>= 1) p += __shfl_down_sync(0xffffffffu, p, o);
            if (l == 0) sc[r * 52 + s] = p + b2v;
        }
    }
    __syncthreads();

    // P4: softmax
    {
        int w = tid >> 5, l = tid & 31;
        if (w < 7) {
            float v0 = (l < 50) ? sc[w * 52 + l] : -1e30f;
            float v1 = (l + 32 < 50) ? sc[w * 52 + l + 32] : -1e30f;
            float mx = fmaxf(v0, v1);
#pragma unroll
            for (int o = 16; o; o >>= 1) mx = fmaxf(mx, __shfl_xor_sync(0xffffffffu, mx, o));
            float e0 = (l < 50) ? __expf(v0 - mx) : 0.0f;
            float e1 = (l + 32 < 50) ? __expf(v1 - mx) : 0.0f;
            float sum = e0 + e1;
#pragma unroll
            for (int o = 16; o; o >>= 1) sum += __shfl_xor_sync(0xffffffffu, sum, o);
            float inv = __fdividef(1.0f, sum);
            if (l < 50) al[w * 52 + l] = e0 * inv;
            if (l + 32 < 50) al[w * 52 + l + 32] = e1 * inv;
        }
    }
    __syncthreads();

    // P5: att_vec
    {
        int h = lane128;
        float acc[4] = {0.f, 0.f, 0.f, 0.f};
        for (int s = 0; s < 50; s++) {
            float ev = eo[s * 128 + h];
#pragma unroll
            for (int u = 0; u < 4; u++) {
                int r = rset + 2 * u;
                if (r < 7) acc[u] += al[r * 52 + s] * ev;
            }
        }
#pragma unroll
        for (int u = 0; u < 4; u++) {
            int r = rset + 2 * u;
            if (r < 7) avs[r * 128 + h] = acc[u];
        }
    }
    __syncthreads();

    // P6: final -> fp16, k-major coalesced weight reads
    {
        int j = lane128;
        float acc[4] = {0.f, 0.f, 0.f, 0.f};
#pragma unroll 2
        for (int k = 0; k < 128; k++) {
            float w0 = __ldg(g_outwT + k * 128 + j);
            float w1 = __ldg(g_outwT + (k + 128) * 128 + j);
#pragma unroll
            for (int u = 0; u < 4; u++) {
                int r = rset + 2 * u;
                if (r < 7)
                    acc[u] += w0 * hsm[r * 128 + k] + w1 * avs[r * 128 + k];
            }
        }
        float bv = out_b[j];
#pragma unroll
        for (int u = 0; u < 4; u++) {
            int r = rset + 2 * u;
            if (r < 7) {
                float fv = ftanh(acc[u] + bv);
                size_t m = (size_t)((t0 + r) * 32 + b) * 128 + j;
                g_Ahi[m] = __half_as_ushort(__float2half_rn(fv));
            }
        }
    }
}

// ---------------- K4: convert sm_w fp32 -> fp16 ------------------------------
__global__ void convB_kernel(const float* __restrict__ w)
{
    int idx = blockIdx.x * 256 + threadIdx.x;   // float4 index
    const int total = VV * 128 / 4;
    for (int i = idx; i < total; i += gridDim.x * 256) {
        float4 v = __ldg((const float4*)w + i);
        ushort4 hv = make_ushort4(
            __half_as_ushort(__float2half_rn(v.x)),
            __half_as_ushort(__float2half_rn(v.y)),
            __half_as_ushort(__float2half_rn(v.z)),
            __half_as_ushort(__float2half_rn(v.w)));
        ((ushort4*)g_Bhi)[i] = hv;
    }
}

// ---------------- K5: fp16 mma.sync single-pass GEMM -------------------------
// D[1568,32000] = A@B^T + bias. CTA tile M=64 x N=128, K=128 smem-resident.
#define GSTR 272
#define OFF_A 0
#define OFF_B (64 * GSTR)                  // 17408
#define GEMM_SMEM (OFF_B + 128 * GSTR)     // 52224 B

__global__ __launch_bounds__(256, 2)
void gemm_kernel(const float* __restrict__ smb, float* __restrict__ outp)
{
    extern __shared__ char smc[];
    u32 sbse = smem_u32(smc);
    int tid = threadIdx.x;
    int n0 = blockIdx.x * 128;
    int m0 = blockIdx.y * 64;

    for (int idx = tid; idx < 64 * 16; idx += 256) {         // A
        int r = idx >> 4, c = idx & 15;
        int m = m0 + r;
        uint4 v = make_uint4(0, 0, 0, 0);
        if (m < 1568) v = ((const uint4*)g_Ahi)[m * 16 + c];
        *(uint4*)(smc + OFF_A + r * GSTR + c * 16) = v;
    }
    for (int idx = tid; idx < 128 * 16; idx += 256) {        // B
        int r = idx >> 4, c = idx & 15;
        int n = n0 + r;
        *(uint4*)(smc + OFF_B + r * GSTR + c * 16) = ((const uint4*)g_Bhi)[n * 16 + c];
    }
    __syncthreads();

    int wid = tid >> 5, l = tid & 31;
    int wm = (wid >> 2) * 32;
    int wn = (wid & 3) * 32;

    u32 aoff = (u32)((wm + (l & 15)) * GSTR + ((l >> 4) << 4));
    u32 boff = (u32)((wn + ((l >> 4) << 3) + (l & 7)) * GSTR + (((l >> 3) & 1) << 4));
    u32 aAddr = sbse + OFF_A + aoff;
    u32 bAddr = sbse + OFF_B + boff;

    float c[2][4][4];
#pragma unroll
    for (int i = 0; i < 2; i++)
#pragma unroll
        for (int j = 0; j < 4; j++)
#pragma unroll
            for (int q = 0; q < 4; q++) c[i][j][q] = 0.0f;

#pragma unroll
    for (int ks = 0; ks < 8; ks++) {
        u32 a0[4], a1[4], b0[4], b1[4];
        ldsm4(a0, aAddr + ks * 32);
        ldsm4(a1, aAddr + 16 * GSTR + ks * 32);
        ldsm4(b0, bAddr + ks * 32);
        ldsm4(b1, bAddr + 16 * GSTR + ks * 32);
        mma16816(c[0][0], a0, b0[0], b0[1]);
        mma16816(c[0][1], a0, b0[2], b0[3]);
        mma16816(c[0][2], a0, b1[0], b1[1]);
        mma16816(c[0][3], a0, b1[2], b1[3]);
        mma16816(c[1][0], a1, b0[0], b0[1]);
        mma16816(c[1][1], a1, b0[2], b0[3]);
        mma16816(c[1][2], a1, b1[0], b1[1]);
        mma16816(c[1][3], a1, b1[2], b1[3]);
    }

#pragma unroll
    for (int nf = 0; nf < 4; nf++) {
        int cb = n0 + wn + nf * 8 + 2 * (l & 3);
        float2 bv = __ldg((const float2*)(smb + cb));
#pragma unroll
        for (int mf = 0; mf < 2; mf++) {
            int mrow = m0 + wm + mf * 16 + (l >> 2);
#pragma unroll
            for (int h = 0; h < 2; h++) {
                int m = mrow + h * 8;
                if (m < 1568) {
                    int t = m >> 5, b = m & 31;
                    float2 o;
                    o.x = c[mf][nf][h * 2 + 0] + bv.x;
                    o.y = c[mf][nf][h * 2 + 1] + bv.y;
                    *(float2*)(outp + (size_t)(b * 49 + t) * 32000 + cb) = o;
                }
            }
        }
    }
}

extern "C" void kernel_launch(void* const* d_in, const int* in_sizes, int n_in,
                              void* d_out, int out_size)
{
    const int*   src     = (const int*)  d_in[0];
    const int*   trg     = (const int*)  d_in[1];
    const float* emb_src = (const float*)d_in[2];
    const float* emb_trg = (const float*)d_in[3];
    const float* enc_Wih = (const float*)d_in[4];
    const float* enc_Whh = (const float*)d_in[5];
    const float* enc_bih = (const float*)d_in[6];
    const float* enc_bhh = (const float*)d_in[7];
    const float* dec_Wih = (const float*)d_in[8];
    const float* dec_Whh = (const float*)d_in[9];
    const float* dec_bih = (const float*)d_in[10];
    const float* dec_bhh = (const float*)d_in[11];
    const float* att_w1s = (const float*)d_in[12];
    const float* att_b1s = (const float*)d_in[13];
    const float* att_w1t = (const float*)d_in[14];
    const float* att_b1t = (const float*)d_in[15];
    const float* att_w2  = (const float*)d_in[16];
    const float* att_b2  = (const float*)d_in[17];
    const float* out_w   = (const float*)d_in[18];
    const float* out_b   = (const float*)d_in[19];
    const float* sm_w    = (const float*)d_in[20];
    const float* sm_b    = (const float*)d_in[21];
    float* outp = (float*)d_out;

    cudaFuncSetAttribute(lstm_kernel,
                         cudaFuncAttributeMaxDynamicSharedMemorySize, LSTM_SMEM);
    cudaFuncSetAttribute(attn_kernel,
                         cudaFuncAttributeMaxDynamicSharedMemorySize, ATTN_SMEM);
    cudaFuncSetAttribute(gemm_kernel,
                         cudaFuncAttributeMaxDynamicSharedMemorySize, GEMM_SMEM);

    prep_kernel<<<256, 256>>>(att_w1t, out_w, att_w1s);
    pre_kernel<<<396, 256>>>(src, trg, emb_src, emb_trg,
                             enc_Wih, enc_bih, enc_bhh,
                             dec_Wih, dec_bih, dec_bhh);
    convB_kernel<<<1000, 256>>>(sm_w);
    lstm_kernel<<<64, 512, LSTM_SMEM>>>(enc_Whh, dec_Whh, att_b1s);
    attn_kernel<<<dim3(32, 7), 256, ATTN_SMEM>>>(att_b1t, att_w2, att_b2, out_b);
    gemm_kernel<<<dim3(250, 25), 256, GEMM_SMEM>>>(sm_b, outp);
}

// round 15
// speedup vs baseline: 1.6073x; 1.4310x over previous
#include <cuda_runtime.h>
#include <cuda_bf16.h>
#include <cuda_fp16.h>
#include <math.h>

#define BB 32
#define SS 50
#define TD 49
#define EE 128
#define HH 128
#define GG 512
#define VV 32000

typedef unsigned long long u64;
typedef unsigned int u32;

// ---------------- device scratch (no allocations allowed) --------------------
__device__ float g_encPre[SS * BB * GG];
__device__ float g_decPre[TD * BB * GG];
__device__ float g_encOut[BB * SS * HH];
__device__ float g_attSrc[BB * SS * HH];
__device__ float g_decH[TD * BB * HH];
__device__ float g_w1tT[128 * 128];            // w1t transposed [k][a]
__device__ float g_outwT[256 * 128];           // out_w transposed [k][j]
__device__ float g_w1sT[128 * 128];            // w1s transposed [k][a]
__device__ unsigned short g_Ahi[1568 * 128];   // finals, fp16
__device__ unsigned short g_Bhi[VV * 128];     // sm_w, fp16

// ---------------- helpers ----------------------------------------------------
__device__ __forceinline__ float sigm(float x) {
    return 1.0f / (1.0f + __expf(-x));
}
__device__ __forceinline__ float ftanh(float x) {
    float e = __expf(-2.0f * fabsf(x));
    float r = __fdividef(1.0f - e, 1.0f + e);
    return copysignf(r, x);
}
__device__ __forceinline__ float htanh(float x) {   // HW MUFU.TANH
    float y;
    asm("tanh.approx.f32 %0, %1;" : "=f"(y) : "f"(x));
    return y;
}
__device__ __forceinline__ u32 smem_u32(const void* p) {
    u32 a;
    asm("{ .reg .u64 t; cvta.to.shared.u64 t, %1; cvt.u32.u64 %0, t; }" : "=r"(a) : "l"(p));
    return a;
}
__device__ __forceinline__ void ldsm4(u32* r, u32 addr) {
    asm volatile("ldmatrix.sync.aligned.m8n8.x4.shared.b16 {%0,%1,%2,%3}, [%4];"
                 : "=r"(r[0]), "=r"(r[1]), "=r"(r[2]), "=r"(r[3]) : "r"(addr));
}
__device__ __forceinline__ void mma16816(float* c, const u32* a, u32 b0, u32 b1) {
    asm volatile(
        "mma.sync.aligned.m16n8k16.row.col.f32.f16.f16.f32 "
        "{%0,%1,%2,%3}, {%4,%5,%6,%7}, {%8,%9}, {%0,%1,%2,%3};"
        : "+f"(c[0]), "+f"(c[1]), "+f"(c[2]), "+f"(c[3])
        : "r"(a[0]), "r"(a[1]), "r"(a[2]), "r"(a[3]), "r"(b0), "r"(b1));
}

// ---------------- K0: transpose small weights to k-major ---------------------
__global__ void prep_kernel(const float* __restrict__ w1t,
                            const float* __restrict__ out_w,
                            const float* __restrict__ w1s)
{
    int i = blockIdx.x * 256 + threadIdx.x;
    if (i < 16384) {
        int k = i >> 7, a = i & 127;
        g_w1tT[i] = w1t[a * 128 + k];
    } else if (i < 49152) {
        int i2 = i - 16384;
        int k = i2 >> 7, j = i2 & 127;
        g_outwT[i2] = out_w[j * 256 + k];
    } else {
        int i2 = i - 49152;
        int k = i2 >> 7, a = i2 & 127;
        g_w1sT[i2] = w1s[a * 128 + k];
    }
}

// ---------------- K1: precompute x @ Wih^T + bih + bhh (enc + dec merged) ----
__global__ void pre_kernel(const int* __restrict__ srcTok,
                           const int* __restrict__ trgTok,
                           const float* __restrict__ embS,
                           const float* __restrict__ embT,
                           const float* __restrict__ eWih,
                           const float* __restrict__ ebih,
                           const float* __restrict__ ebhh,
                           const float* __restrict__ dWih,
                           const float* __restrict__ dbih,
                           const float* __restrict__ dbhh)
{
    int bid = blockIdx.x;
    int which = (bid >= 200);
    const int*   tok = which ? trgTok : srcTok;
    const float* emb = which ? embT   : embS;
    const float* Wih = which ? dWih   : eWih;
    const float* bih = which ? dbih   : ebih;
    const float* bhh = which ? dbhh   : ebhh;
    float* outp      = which ? g_decPre : g_encPre;
    int Tlen         = which ? TD : SS;
    int p0 = (which ? bid - 200 : bid) * 8;

    __shared__ float es[8][128];
    int tid = threadIdx.x;
    int total = Tlen * BB;
    for (int idx = tid; idx < 8 * 128; idx += 256) {
        int pi = idx >> 7, kk = idx & 127;
        int p = p0 + pi;
        float v = 0.0f;
        if (p < total) {
            int t = p >> 5, b = p & 31;
            int tv = tok[b * SS + t];
            v = emb[(size_t)tv * EE + kk];
        }
        es[pi][kk] = v;
    }
    __syncthreads();
    int j0 = tid, j1 = tid + 256;
    float acc0[8], acc1[8];
    float bi0 = bih[j0] + bhh[j0];
    float bi1 = bih[j1] + bhh[j1];
#pragma unroll
    for (int pi = 0; pi < 8; pi++) { acc0[pi] = bi0; acc1[pi] = bi1; }
    const float4* w0 = (const float4*)(Wih + (size_t)j0 * EE);
    const float4* w1 = (const float4*)(Wih + (size_t)j1 * EE);
    for (int q = 0; q < 32; q++) {
        float4 a = w0[q];
        float4 c = w1[q];
#pragma unroll
        for (int pi = 0; pi < 8; pi++) {
            float4 e = *(const float4*)&es[pi][q * 4];
            acc0[pi] += a.x * e.x + a.y * e.y + a.z * e.z + a.w * e.w;
            acc1[pi] += c.x * e.x + c.y * e.y + c.z * e.z + c.w * e.w;
        }
    }
    for (int pi = 0; pi < 8; pi++) {
        int p = p0 + pi;
        if (p < total) {
            outp[(size_t)p * GG + j0] = acc0[pi];
            outp[(size_t)p * GG + j1] = acc1[pi];
        }
    }
}

// ---------------- K2: merged LSTM recurrences + fused att_src ----------------
// 48 K-cols in registers (12 float4), 80 K-cols in row-major smem [j][k],
// row stride 84 floats (336 B: lane banks (20j)%32, conflict-free phases).
// Per step: LDS.128 x20 with prefetch-distance-2 double buffer, 2 accumulators.
#define WSTR 84
#define LSTM_SMEM ((512 * WSTR + 50 * 128 + 128 + 128 + 512) * 4)

__global__ __launch_bounds__(512, 1)
void lstm_kernel(const float* __restrict__ eWhh,
                 const float* __restrict__ dWhh,
                 const float* __restrict__ b1s)
{
    extern __shared__ float sm[];
    float* sW   = sm;                       // [512 j][84 (80 used)]
    float* hist = sm + 512 * WSTR;          // [50][128]
    float* hs   = hist + 50 * 128;
    float* cs   = hs + 128;
    float* gbuf = cs + 128;

    int bid = blockIdx.x;
    int which = (bid >= 32);
    int b = bid & 31;
    const float* Whh = which ? dWhh : eWhh;
    const float* pre = which ? g_decPre : g_encPre;
    int steps = which ? TD : SS;
    int tid = threadIdx.x, j = tid;

    // registers: K columns 0..47
    float4 wr[12];
    const float4* wrow = (const float4*)(Whh + (size_t)j * 128);
#pragma unroll
    for (int q = 0; q < 12; q++) wr[q] = wrow[q];
    // smem: K columns 48..127, own-row contiguous
    for (int idx = tid; idx < 512 * 80; idx += 512) {
        int jj = idx & 511, kk = idx >> 9;
        sW[jj * WSTR + kk] = Whh[(size_t)jj * 128 + 48 + kk];
    }
    if (tid < 128) { hs[tid] = 0.0f; cs[tid] = 0.0f; }
    __syncthreads();

    const float4* wj4 = (const float4*)(sW + j * WSTR);   // 20 float4 chunks
    const float* preB = pre + (size_t)b * GG;
    float cur = preB[j];
    for (int t = 0; t < steps; t++) {
        const float4* h4 = (const float4*)hs;
        float4 p0 = wj4[0], p1 = wj4[1];
        float a0 = cur, a1 = 0.0f;
#pragma unroll
        for (int q = 0; q < 12; q++) {
            float4 hv = h4[q];
            a0 += wr[q].x * hv.x + wr[q].y * hv.y;
            a1 += wr[q].z * hv.z + wr[q].w * hv.w;
        }
#pragma unroll
        for (int c = 0; c < 20; c++) {
            float4 w = p0;
            p0 = p1;
            if (c < 18) p1 = wj4[c + 2];
            float4 hv = h4[12 + c];
            a0 += w.x * hv.x + w.y * hv.y;
            a1 += w.z * hv.z + w.w * hv.w;
        }
        gbuf[j] = a0 + a1;
        __syncthreads();
        if (t + 1 < steps) cur = preB[(size_t)(t + 1) * BB * GG + j];
        if (tid < 128) {
            float ig = gbuf[tid], fg = gbuf[128 + tid];
            float gg = gbuf[256 + tid], og = gbuf[384 + tid];
            float cc = sigm(fg) * cs[tid] + sigm(ig) * ftanh(gg);
            float hv = sigm(og) * ftanh(cc);
            cs[tid] = cc;
            hs[tid] = hv;
            if (which) {
                g_decH[(size_t)(t * 32 + b) * 128 + tid] = hv;
            } else {
                hist[t * 128 + tid] = hv;
                g_encOut[(size_t)(b * 50 + t) * 128 + tid] = hv;
            }
        }
        __syncthreads();
    }

    // fused att_src (encoder CTAs), k-major coalesced weight reads
    if (!which) {
        int a = tid & 127;
        int sB = tid >> 7;
        const float* hp[13];
#pragma unroll
        for (int q = 0; q < 13; q++) {
            int s = sB + 4 * q;
            hp[q] = hist + (s < 50 ? s : 49) * 128;
        }
        float accv[13];
#pragma unroll
        for (int q = 0; q < 13; q++) accv[q] = 0.0f;
#pragma unroll 2
        for (int k = 0; k < 128; k++) {
            float w = __ldg(g_w1sT + k * 128 + a);
#pragma unroll
            for (int q = 0; q < 13; q++) accv[q] += hp[q][k] * w;
        }
        float bv = b1s[a];
#pragma unroll
        for (int q = 0; q < 13; q++) {
            int s = sB + 4 * q;
            if (s < 50) g_attSrc[(size_t)(b * 50 + s) * 128 + a] = accv[q] + bv;
        }
    }
}

// ---------------- K3: batched attention + final (7 t's per CTA) --------------
#define AT_ASRC 0
#define AT_EO   6400
#define AT_HS   12800
#define AT_ATG  13696
#define AT_AVS  14592
#define AT_SC   15488
#define AT_AL   15852
#define ATTN_SMEM (16216 * 4)

__global__ __launch_bounds__(256, 3)
void attn_kernel(const float* __restrict__ b1t,
                 const float* __restrict__ w2,
                 const float* __restrict__ b2,
                 const float* __restrict__ out_b)
{
    extern __shared__ float sb[];
    float* asrc = sb + AT_ASRC;
    float* eo   = sb + AT_EO;
    float* hsm  = sb + AT_HS;    // [7][128]
    float* atg  = sb + AT_ATG;   // [7][128]
    float* avs  = sb + AT_AVS;   // [7][128]
    float* sc   = sb + AT_SC;    // [7][52]
    float* al   = sb + AT_AL;    // [7][52]

    int b = blockIdx.x;
    int t0 = blockIdx.y * 7;
    int tid = threadIdx.x;

    {
        const float4* ga = (const float4*)(g_attSrc + (size_t)(b * 50) * 128);
        const float4* ge = (const float4*)(g_encOut + (size_t)(b * 50) * 128);
        for (int i = tid; i < 1600; i += 256) {
            ((float4*)asrc)[i] = ga[i];
            ((float4*)eo)[i]   = ge[i];
        }
        for (int i = tid; i < 7 * 128; i += 256) {
            int r = i >> 7, k = i & 127;
            hsm[i] = g_decH[(size_t)((t0 + r) * 32 + b) * 128 + k];
        }
    }
    __syncthreads();

    int lane128 = tid & 127;
    int rset = tid >> 7;

    // P2: att_tgt, k-major coalesced weight reads
    {
        int a = lane128;
        float acc[4] = {0.f, 0.f, 0.f, 0.f};
#pragma unroll 2
        for (int k = 0; k < 128; k++) {
            float w = __ldg(g_w1tT + k * 128 + a);
#pragma unroll
            for (int u = 0; u < 4; u++) {
                int r = rset + 2 * u;
                if (r < 7) acc[u] += w * hsm[r * 128 + k];
            }
        }
        float bv = b1t[a];
#pragma unroll
        for (int u = 0; u < 4; u++) {
            int r = rset + 2 * u;
            if (r < 7) atg[r * 128 + a] = acc[u] + bv;
        }
    }
    __syncthreads();

    // P3: scores
    {
        int w = tid >> 5, l = tid & 31;
        float4 wv = __ldg((const float4*)w2 + l);
        float b2v = b2[0];
        for (int task = w; task < 350; task += 8) {
            int r = task / 50, s = task - r * 50;
            float4 av = *(const float4*)&asrc[s * 128 + l * 4];
            float4 tg = *(const float4*)&atg[r * 128 + l * 4];
            float p = htanh(av.x + tg.x) * wv.x + htanh(av.y + tg.y) * wv.y
                    + htanh(av.z + tg.z) * wv.z + htanh(av.w + tg.w) * wv.w;
#pragma unroll
            for (int o = 16; o; o >>= 1) p += __shfl_down_sync(0xffffffffu, p, o);
            if (l == 0) sc[r * 52 + s] = p + b2v;
        }
    }
    __syncthreads();

    // P4: softmax
    {
        int w = tid >> 5, l = tid & 31;
        if (w < 7) {
            float v0 = (l < 50) ? sc[w * 52 + l] : -1e30f;
            float v1 = (l + 32 < 50) ? sc[w * 52 + l + 32] : -1e30f;
            float mx = fmaxf(v0, v1);
#pragma unroll
            for (int o = 16; o; o >>= 1) mx = fmaxf(mx, __shfl_xor_sync(0xffffffffu, mx, o));
            float e0 = (l < 50) ? __expf(v0 - mx) : 0.0f;
            float e1 = (l + 32 < 50) ? __expf(v1 - mx) : 0.0f;
            float sum = e0 + e1;
#pragma unroll
            for (int o = 16; o; o >>= 1) sum += __shfl_xor_sync(0xffffffffu, sum, o);
            float inv = __fdividef(1.0f, sum);
            if (l < 50) al[w * 52 + l] = e0 * inv;
            if (l + 32 < 50) al[w * 52 + l + 32] = e1 * inv;
        }
    }
    __syncthreads();

    // P5: att_vec
    {
        int h = lane128;
        float acc[4] = {0.f, 0.f, 0.f, 0.f};
        for (int s = 0; s < 50; s++) {
            float ev = eo[s * 128 + h];
#pragma unroll
            for (int u = 0; u < 4; u++) {
                int r = rset + 2 * u;
                if (r < 7) acc[u] += al[r * 52 + s] * ev;
            }
        }
#pragma unroll
        for (int u = 0; u < 4; u++) {
            int r = rset + 2 * u;
            if (r < 7) avs[r * 128 + h] = acc[u];
        }
    }
    __syncthreads();

    // P6: final -> fp16, k-major coalesced weight reads
    {
        int j = lane128;
        float acc[4] = {0.f, 0.f, 0.f, 0.f};
#pragma unroll 2
        for (int k = 0; k < 128; k++) {
            float w0 = __ldg(g_outwT + k * 128 + j);
            float w1 = __ldg(g_outwT + (k + 128) * 128 + j);
#pragma unroll
            for (int u = 0; u < 4; u++) {
                int r = rset + 2 * u;
                if (r < 7)
                    acc[u] += w0 * hsm[r * 128 + k] + w1 * avs[r * 128 + k];
            }
        }
        float bv = out_b[j];
#pragma unroll
        for (int u = 0; u < 4; u++) {
            int r = rset + 2 * u;
            if (r < 7) {
                float fv = ftanh(acc[u] + bv);
                size_t m = (size_t)((t0 + r) * 32 + b) * 128 + j;
                g_Ahi[m] = __half_as_ushort(__float2half_rn(fv));
            }
        }
    }
}

// ---------------- K4: convert sm_w fp32 -> fp16 ------------------------------
__global__ void convB_kernel(const float* __restrict__ w)
{
    int idx = blockIdx.x * 256 + threadIdx.x;   // float4 index
    const int total = VV * 128 / 4;
    for (int i = idx; i < total; i += gridDim.x * 256) {
        float4 v = __ldg((const float4*)w + i);
        ushort4 hv = make_ushort4(
            __half_as_ushort(__float2half_rn(v.x)),
            __half_as_ushort(__float2half_rn(v.y)),
            __half_as_ushort(__float2half_rn(v.z)),
            __half_as_ushort(__float2half_rn(v.w)));
        ((ushort4*)g_Bhi)[i] = hv;
    }
}

// ---------------- K5: fp16 mma.sync single-pass GEMM -------------------------
#define GSTR 272
#define OFF_A 0
#define OFF_B (64 * GSTR)                  // 17408
#define GEMM_SMEM (OFF_B + 128 * GSTR)     // 52224 B

__global__ __launch_bounds__(256, 2)
void gemm_kernel(const float* __restrict__ smb, float* __restrict__ outp)
{
    extern __shared__ char smc[];
    u32 sbse = smem_u32(smc);
    int tid = threadIdx.x;
    int n0 = blockIdx.x * 128;
    int m0 = blockIdx.y * 64;

    for (int idx = tid; idx < 64 * 16; idx += 256) {         // A
        int r = idx >> 4, c = idx & 15;
        int m = m0 + r;
        uint4 v = make_uint4(0, 0, 0, 0);
        if (m < 1568) v = ((const uint4*)g_Ahi)[m * 16 + c];
        *(uint4*)(smc + OFF_A + r * GSTR + c * 16) = v;
    }
    for (int idx = tid; idx < 128 * 16; idx += 256) {        // B
        int r = idx >> 4, c = idx & 15;
        int n = n0 + r;
        *(uint4*)(smc + OFF_B + r * GSTR + c * 16) = ((const uint4*)g_Bhi)[n * 16 + c];
    }
    __syncthreads();

    int wid = tid >> 5, l = tid & 31;
    int wm = (wid >> 2) * 32;
    int wn = (wid & 3) * 32;

    u32 aoff = (u32)((wm + (l & 15)) * GSTR + ((l >> 4) << 4));
    u32 boff = (u32)((wn + ((l >> 4) << 3) + (l & 7)) * GSTR + (((l >> 3) & 1) << 4));
    u32 aAddr = sbse + OFF_A + aoff;
    u32 bAddr = sbse + OFF_B + boff;

    float c[2][4][4];
#pragma unroll
    for (int i = 0; i < 2; i++)
#pragma unroll
        for (int j = 0; j < 4; j++)
#pragma unroll
            for (int q = 0; q < 4; q++) c[i][j][q] = 0.0f;

#pragma unroll
    for (int ks = 0; ks < 8; ks++) {
        u32 a0[4], a1[4], b0[4], b1[4];
        ldsm4(a0, aAddr + ks * 32);
        ldsm4(a1, aAddr + 16 * GSTR + ks * 32);
        ldsm4(b0, bAddr + ks * 32);
        ldsm4(b1, bAddr + 16 * GSTR + ks * 32);
        mma16816(c[0][0], a0, b0[0], b0[1]);
        mma16816(c[0][1], a0, b0[2], b0[3]);
        mma16816(c[0][2], a0, b1[0], b1[1]);
        mma16816(c[0][3], a0, b1[2], b1[3]);
        mma16816(c[1][0], a1, b0[0], b0[1]);
        mma16816(c[1][1], a1, b0[2], b0[3]);
        mma16816(c[1][2], a1, b1[0], b1[1]);
        mma16816(c[1][3], a1, b1[2], b1[3]);
    }

#pragma unroll
    for (int nf = 0; nf < 4; nf++) {
        int cb = n0 + wn + nf * 8 + 2 * (l & 3);
        float2 bv = __ldg((const float2*)(smb + cb));
#pragma unroll
        for (int mf = 0; mf < 2; mf++) {
            int mrow = m0 + wm + mf * 16 + (l >> 2);
#pragma unroll
            for (int h = 0; h < 2; h++) {
                int m = mrow + h * 8;
                if (m < 1568) {
                    int t = m >> 5, b = m & 31;
                    float2 o;
                    o.x = c[mf][nf][h * 2 + 0] + bv.x;
                    o.y = c[mf][nf][h * 2 + 1] + bv.y;
                    *(float2*)(outp + (size_t)(b * 49 + t) * 32000 + cb) = o;
                }
            }
        }
    }
}

extern "C" void kernel_launch(void* const* d_in, const int* in_sizes, int n_in,
                              void* d_out, int out_size)
{
    const int*   src     = (const int*)  d_in[0];
    const int*   trg     = (const int*)  d_in[1];
    const float* emb_src = (const float*)d_in[2];
    const float* emb_trg = (const float*)d_in[3];
    const float* enc_Wih = (const float*)d_in[4];
    const float* enc_Whh = (const float*)d_in[5];
    const float* enc_bih = (const float*)d_in[6];
    const float* enc_bhh = (const float*)d_in[7];
    const float* dec_Wih = (const float*)d_in[8];
    const float* dec_Whh = (const float*)d_in[9];
    const float* dec_bih = (const float*)d_in[10];
    const float* dec_bhh = (const float*)d_in[11];
    const float* att_w1s = (const float*)d_in[12];
    const float* att_b1s = (const float*)d_in[13];
    const float* att_w1t = (const float*)d_in[14];
    const float* att_b1t = (const float*)d_in[15];
    const float* att_w2  = (const float*)d_in[16];
    const float* att_b2  = (const float*)d_in[17];
    const float* out_w   = (const float*)d_in[18];
    const float* out_b   = (const float*)d_in[19];
    const float* sm_w    = (const float*)d_in[20];
    const float* sm_b    = (const float*)d_in[21];
    float* outp = (float*)d_out;

    cudaFuncSetAttribute(lstm_kernel,
                         cudaFuncAttributeMaxDynamicSharedMemorySize, LSTM_SMEM);
    cudaFuncSetAttribute(attn_kernel,
                         cudaFuncAttributeMaxDynamicSharedMemorySize, ATTN_SMEM);
    cudaFuncSetAttribute(gemm_kernel,
                         cudaFuncAttributeMaxDynamicSharedMemorySize, GEMM_SMEM);

    prep_kernel<<<256, 256>>>(att_w1t, out_w, att_w1s);
    pre_kernel<<<396, 256>>>(src, trg, emb_src, emb_trg,
                             enc_Wih, enc_bih, enc_bhh,
                             dec_Wih, dec_bih, dec_bhh);
    convB_kernel<<<1000, 256>>>(sm_w);
    lstm_kernel<<<64, 512, LSTM_SMEM>>>(enc_Whh, dec_Whh, att_b1s);
    attn_kernel<<<dim3(32, 7), 256, ATTN_SMEM>>>(att_b1t, att_w2, att_b2, out_b);
    gemm_kernel<<<dim3(250, 25), 256, GEMM_SMEM>>>(sm_b, outp);
}

// round 17
// speedup vs baseline: 1.6130x; 1.0035x over previous
#include <cuda_runtime.h>
#include <cuda_bf16.h>
#include <cuda_fp16.h>
#include <math.h>

#define BB 32
#define SS 50
#define TD 49
#define EE 128
#define HH 128
#define GG 512
#define VV 32000

typedef unsigned long long u64;
typedef unsigned int u32;

// ---------------- device scratch (no allocations allowed) --------------------
__device__ float g_encPre[SS * BB * GG];
__device__ float g_decPre[TD * BB * GG];
__device__ float g_encOut[BB * SS * HH];
__device__ float g_attSrc[BB * SS * HH];
__device__ float g_decH[TD * BB * HH];
__device__ float g_w1tT[128 * 128];            // w1t transposed [k][a]
__device__ float g_outwT[256 * 128];           // out_w transposed [k][j]
__device__ float g_w1sT[128 * 128];            // w1s transposed [k][a]
__device__ unsigned short g_Ahi[1568 * 128];   // finals, fp16
__device__ unsigned short g_Bhi[VV * 128];     // sm_w, fp16

// ---------------- helpers ----------------------------------------------------
__device__ __forceinline__ float sigm(float x) {
    return 1.0f / (1.0f + __expf(-x));
}
__device__ __forceinline__ float ftanh(float x) {
    float e = __expf(-2.0f * fabsf(x));
    float r = __fdividef(1.0f - e, 1.0f + e);
    return copysignf(r, x);
}
__device__ __forceinline__ float htanh(float x) {   // HW MUFU.TANH
    float y;
    asm("tanh.approx.f32 %0, %1;" : "=f"(y) : "f"(x));
    return y;
}
__device__ __forceinline__ u32 smem_u32(const void* p) {
    u32 a;
    asm("{ .reg .u64 t; cvta.to.shared.u64 t, %1; cvt.u32.u64 %0, t; }" : "=r"(a) : "l"(p));
    return a;
}
__device__ __forceinline__ void ldsm4(u32* r, u32 addr) {
    asm volatile("ldmatrix.sync.aligned.m8n8.x4.shared.b16 {%0,%1,%2,%3}, [%4];"
                 : "=r"(r[0]), "=r"(r[1]), "=r"(r[2]), "=r"(r[3]) : "r"(addr));
}
__device__ __forceinline__ void mma16816(float* c, const u32* a, u32 b0, u32 b1) {
    asm volatile(
        "mma.sync.aligned.m16n8k16.row.col.f32.f16.f16.f32 "
        "{%0,%1,%2,%3}, {%4,%5,%6,%7}, {%8,%9}, {%0,%1,%2,%3};"
        : "+f"(c[0]), "+f"(c[1]), "+f"(c[2]), "+f"(c[3])
        : "r"(a[0]), "r"(a[1]), "r"(a[2]), "r"(a[3]), "r"(b0), "r"(b1));
}

// ---------------- K0: transpose small weights to k-major ---------------------
__global__ void prep_kernel(const float* __restrict__ w1t,
                            const float* __restrict__ out_w,
                            const float* __restrict__ w1s)
{
    int i = blockIdx.x * 256 + threadIdx.x;
    if (i < 16384) {
        int k = i >> 7, a = i & 127;
        g_w1tT[i] = w1t[a * 128 + k];
    } else if (i < 49152) {
        int i2 = i - 16384;
        int k = i2 >> 7, j = i2 & 127;
        g_outwT[i2] = out_w[j * 256 + k];
    } else {
        int i2 = i - 49152;
        int k = i2 >> 7, a = i2 & 127;
        g_w1sT[i2] = w1s[a * 128 + k];
    }
}

// ---------------- K1: precompute x @ Wih^T + bih + bhh (enc + dec merged) ----
__global__ void pre_kernel(const int* __restrict__ srcTok,
                           const int* __restrict__ trgTok,
                           const float* __restrict__ embS,
                           const float* __restrict__ embT,
                           const float* __restrict__ eWih,
                           const float* __restrict__ ebih,
                           const float* __restrict__ ebhh,
                           const float* __restrict__ dWih,
                           const float* __restrict__ dbih,
                           const float* __restrict__ dbhh)
{
    int bid = blockIdx.x;
    int which = (bid >= 200);
    const int*   tok = which ? trgTok : srcTok;
    const float* emb = which ? embT   : embS;
    const float* Wih = which ? dWih   : eWih;
    const float* bih = which ? dbih   : ebih;
    const float* bhh = which ? dbhh   : ebhh;
    float* outp      = which ? g_decPre : g_encPre;
    int Tlen         = which ? TD : SS;
    int p0 = (which ? bid - 200 : bid) * 8;

    __shared__ float es[8][128];
    int tid = threadIdx.x;
    int total = Tlen * BB;
    for (int idx = tid; idx < 8 * 128; idx += 256) {
        int pi = idx >> 7, kk = idx & 127;
        int p = p0 + pi;
        float v = 0.0f;
        if (p < total) {
            int t = p >> 5, b = p & 31;
            int tv = tok[b * SS + t];
            v = emb[(size_t)tv * EE + kk];
        }
        es[pi][kk] = v;
    }
    __syncthreads();
    int j0 = tid, j1 = tid + 256;
    float acc0[8], acc1[8];
    float bi0 = bih[j0] + bhh[j0];
    float bi1 = bih[j1] + bhh[j1];
#pragma unroll
    for (int pi = 0; pi < 8; pi++) { acc0[pi] = bi0; acc1[pi] = bi1; }
    const float4* w0 = (const float4*)(Wih + (size_t)j0 * EE);
    const float4* w1 = (const float4*)(Wih + (size_t)j1 * EE);
    for (int q = 0; q < 32; q++) {
        float4 a = w0[q];
        float4 c = w1[q];
#pragma unroll
        for (int pi = 0; pi < 8; pi++) {
            float4 e = *(const float4*)&es[pi][q * 4];
            acc0[pi] += a.x * e.x + a.y * e.y + a.z * e.z + a.w * e.w;
            acc1[pi] += c.x * e.x + c.y * e.y + c.z * e.z + c.w * e.w;
        }
    }
    for (int pi = 0; pi < 8; pi++) {
        int p = p0 + pi;
        if (p < total) {
            outp[(size_t)p * GG + j0] = acc0[pi];
            outp[(size_t)p * GG + j1] = acc1[pi];
        }
    }
}

// ---------------- K2: merged LSTM recurrences + fused att_src ----------------
// 48 K-cols in registers, 80 in row-major smem (stride 84, conflict-free).
// Activations distributed across all 512 threads (warp-uniform gate select);
// next-step gate precompute issued at the TOP of each iteration.
#define WSTR 84
#define LSTM_SMEM ((512 * WSTR + 50 * 128 + 128 + 128 + 512) * 4)

__global__ __launch_bounds__(512, 1)
void lstm_kernel(const float* __restrict__ eWhh,
                 const float* __restrict__ dWhh,
                 const float* __restrict__ b1s)
{
    extern __shared__ float sm[];
    float* sW   = sm;                       // [512 j][84 (80 used)]
    float* hist = sm + 512 * WSTR;          // [50][128]
    float* hs   = hist + 50 * 128;
    float* cs   = hs + 128;
    float* gbuf = cs + 128;

    int bid = blockIdx.x;
    int which = (bid >= 32);
    int b = bid & 31;
    const float* Whh = which ? dWhh : eWhh;
    const float* pre = which ? g_decPre : g_encPre;
    int steps = which ? TD : SS;
    int tid = threadIdx.x, j = tid;
    int gsel = j >> 7;                      // 0:i 1:f 2:g 3:o (warp-uniform)

    float4 wr[12];
    const float4* wrow = (const float4*)(Whh + (size_t)j * 128);
#pragma unroll
    for (int q = 0; q < 12; q++) wr[q] = wrow[q];
    for (int idx = tid; idx < 512 * 80; idx += 512) {
        int jj = idx & 511, kk = idx >> 9;
        sW[jj * WSTR + kk] = Whh[(size_t)jj * 128 + 48 + kk];
    }
    if (tid < 128) { hs[tid] = 0.0f; cs[tid] = 0.0f; }
    __syncthreads();

    const float4* wj4 = (const float4*)(sW + j * WSTR);   // 20 float4 chunks
    const float* preB = pre + (size_t)b * GG;
    float cur = preB[j];
    for (int t = 0; t < steps; t++) {
        // issue next step's gate-precompute load NOW; consumed next iteration
        float nxt = 0.0f;
        if (t + 1 < steps) nxt = preB[(size_t)(t + 1) * BB * GG + j];

        const float4* h4 = (const float4*)hs;
        float4 p0 = wj4[0], p1 = wj4[1];
        float a0 = cur, a1 = 0.0f;
#pragma unroll
        for (int q = 0; q < 12; q++) {
            float4 hv = h4[q];
            a0 += wr[q].x * hv.x + wr[q].y * hv.y;
            a1 += wr[q].z * hv.z + wr[q].w * hv.w;
        }
#pragma unroll
        for (int c = 0; c < 20; c++) {
            float4 w = p0;
            p0 = p1;
            if (c < 18) p1 = wj4[c + 2];
            float4 hv = h4[12 + c];
            a0 += w.x * hv.x + w.y * hv.y;
            a1 += w.z * hv.z + w.w * hv.w;
        }
        float gv = a0 + a1;
        // distributed activation: i/f/o -> sigmoid, g -> tanh (warp-uniform)
        gbuf[j] = (gsel == 2) ? ftanh(gv) : sigm(gv);
        cur = nxt;
        __syncthreads();
        if (tid < 128) {
            float ia = gbuf[tid],       fa = gbuf[128 + tid];
            float ga = gbuf[256 + tid], oa = gbuf[384 + tid];
            float cc = fa * cs[tid] + ia * ga;
            float hv = oa * ftanh(cc);
            cs[tid] = cc;
            hs[tid] = hv;
            if (which) {
                g_decH[(size_t)(t * 32 + b) * 128 + tid] = hv;
            } else {
                hist[t * 128 + tid] = hv;
                g_encOut[(size_t)(b * 50 + t) * 128 + tid] = hv;
            }
        }
        __syncthreads();
    }

    // fused att_src (encoder CTAs), k-major coalesced weight reads
    if (!which) {
        int a = tid & 127;
        int sB = tid >> 7;
        const float* hp[13];
#pragma unroll
        for (int q = 0; q < 13; q++) {
            int s = sB + 4 * q;
            hp[q] = hist + (s < 50 ? s : 49) * 128;
        }
        float accv[13];
#pragma unroll
        for (int q = 0; q < 13; q++) accv[q] = 0.0f;
#pragma unroll 2
        for (int k = 0; k < 128; k++) {
            float w = __ldg(g_w1sT + k * 128 + a);
#pragma unroll
            for (int q = 0; q < 13; q++) accv[q] += hp[q][k] * w;
        }
        float bv = b1s[a];
#pragma unroll
        for (int q = 0; q < 13; q++) {
            int s = sB + 4 * q;
            if (s < 50) g_attSrc[(size_t)(b * 50 + s) * 128 + a] = accv[q] + bv;
        }
    }
}

// ---------------- K3: batched attention + final (7 t's per CTA) --------------
#define AT_ASRC 0
#define AT_EO   6400
#define AT_HS   12800
#define AT_ATG  13696
#define AT_AVS  14592
#define AT_SC   15488
#define AT_AL   15852
#define ATTN_SMEM (16216 * 4)

__global__ __launch_bounds__(256, 3)
void attn_kernel(const float* __restrict__ b1t,
                 const float* __restrict__ w2,
                 const float* __restrict__ b2,
                 const float* __restrict__ out_b)
{
    extern __shared__ float sb[];
    float* asrc = sb + AT_ASRC;
    float* eo   = sb + AT_EO;
    float* hsm  = sb + AT_HS;    // [7][128]
    float* atg  = sb + AT_ATG;   // [7][128]
    float* avs  = sb + AT_AVS;   // [7][128]
    float* sc   = sb + AT_SC;    // [7][52]
    float* al   = sb + AT_AL;    // [7][52]

    int b = blockIdx.x;
    int t0 = blockIdx.y * 7;
    int tid = threadIdx.x;

    {
        const float4* ga = (const float4*)(g_attSrc + (size_t)(b * 50) * 128);
        const float4* ge = (const float4*)(g_encOut + (size_t)(b * 50) * 128);
        for (int i = tid; i < 1600; i += 256) {
            ((float4*)asrc)[i] = ga[i];
            ((float4*)eo)[i]   = ge[i];
        }
        for (int i = tid; i < 7 * 128; i += 256) {
            int r = i >> 7, k = i & 127;
            hsm[i] = g_decH[(size_t)((t0 + r) * 32 + b) * 128 + k];
        }
    }
    __syncthreads();

    int lane128 = tid & 127;
    int rset = tid >> 7;

    // P2: att_tgt, k-major coalesced weight reads
    {
        int a = lane128;
        float acc[4] = {0.f, 0.f, 0.f, 0.f};
#pragma unroll 2
        for (int k = 0; k < 128; k++) {
            float w = __ldg(g_w1tT + k * 128 + a);
#pragma unroll
            for (int u = 0; u < 4; u++) {
                int r = rset + 2 * u;
                if (r < 7) acc[u] += w * hsm[r * 128 + k];
            }
        }
        float bv = b1t[a];
#pragma unroll
        for (int u = 0; u < 4; u++) {
            int r = rset + 2 * u;
            if (r < 7) atg[r * 128 + a] = acc[u] + bv;
        }
    }
    __syncthreads();

    // P3: scores
    {
        int w = tid >> 5, l = tid & 31;
        float4 wv = __ldg((const float4*)w2 + l);
        float b2v = b2[0];
        for (int task = w; task < 350; task += 8) {
            int r = task / 50, s = task - r * 50;
            float4 av = *(const float4*)&asrc[s * 128 + l * 4];
            float4 tg = *(const float4*)&atg[r * 128 + l * 4];
            float p = htanh(av.x + tg.x) * wv.x + htanh(av.y + tg.y) * wv.y
                    + htanh(av.z + tg.z) * wv.z + htanh(av.w + tg.w) * wv.w;
#pragma unroll
            for (int o = 16; o; o >>= 1) p += __shfl_down_sync(0xffffffffu, p, o);
            if (l == 0) sc[r * 52 + s] = p + b2v;
        }
    }
    __syncthreads();

    // P4: softmax
    {
        int w = tid >> 5, l = tid & 31;
        if (w < 7) {
            float v0 = (l < 50) ? sc[w * 52 + l] : -1e30f;
            float v1 = (l + 32 < 50) ? sc[w * 52 + l + 32] : -1e30f;
            float mx = fmaxf(v0, v1);
#pragma unroll
            for (int o = 16; o; o >>= 1) mx = fmaxf(mx, __shfl_xor_sync(0xffffffffu, mx, o));
            float e0 = (l < 50) ? __expf(v0 - mx) : 0.0f;
            float e1 = (l + 32 < 50) ? __expf(v1 - mx) : 0.0f;
            float sum = e0 + e1;
#pragma unroll
            for (int o = 16; o; o >>= 1) sum += __shfl_xor_sync(0xffffffffu, sum, o);
            float inv = __fdividef(1.0f, sum);
            if (l < 50) al[w * 52 + l] = e0 * inv;
            if (l + 32 < 50) al[w * 52 + l + 32] = e1 * inv;
        }
    }
    __syncthreads();

    // P5: att_vec
    {
        int h = lane128;
        float acc[4] = {0.f, 0.f, 0.f, 0.f};
        for (int s = 0; s < 50; s++) {
            float ev = eo[s * 128 + h];
#pragma unroll
            for (int u = 0; u < 4; u++) {
                int r = rset + 2 * u;
                if (r < 7) acc[u] += al[r * 52 + s] * ev;
            }
        }
#pragma unroll
        for (int u = 0; u < 4; u++) {
            int r = rset + 2 * u;
            if (r < 7) avs[r * 128 + h] = acc[u];
        }
    }
    __syncthreads();

    // P6: final -> fp16, k-major coalesced weight reads
    {
        int j = lane128;
        float acc[4] = {0.f, 0.f, 0.f, 0.f};
#pragma unroll 2
        for (int k = 0; k < 128; k++) {
            float w0 = __ldg(g_outwT + k * 128 + j);
            float w1 = __ldg(g_outwT + (k + 128) * 128 + j);
#pragma unroll
            for (int u = 0; u < 4; u++) {
                int r = rset + 2 * u;
                if (r < 7)
                    acc[u] += w0 * hsm[r * 128 + k] + w1 * avs[r * 128 + k];
            }
        }
        float bv = out_b[j];
#pragma unroll
        for (int u = 0; u < 4; u++) {
            int r = rset + 2 * u;
            if (r < 7) {
                float fv = ftanh(acc[u] + bv);
                size_t m = (size_t)((t0 + r) * 32 + b) * 128 + j;
                g_Ahi[m] = __half_as_ushort(__float2half_rn(fv));
            }
        }
    }
}

// ---------------- K4: convert sm_w fp32 -> fp16 ------------------------------
__global__ void convB_kernel(const float* __restrict__ w)
{
    int idx = blockIdx.x * 256 + threadIdx.x;   // float4 index
    const int total = VV * 128 / 4;
    for (int i = idx; i < total; i += gridDim.x * 256) {
        float4 v = __ldg((const float4*)w + i);
        ushort4 hv = make_ushort4(
            __half_as_ushort(__float2half_rn(v.x)),
            __half_as_ushort(__float2half_rn(v.y)),
            __half_as_ushort(__float2half_rn(v.z)),
            __half_as_ushort(__float2half_rn(v.w)));
        ((ushort4*)g_Bhi)[i] = hv;
    }
}

// ---------------- K5: fp16 mma.sync single-pass GEMM -------------------------
#define GSTR 272
#define OFF_A 0
#define OFF_B (64 * GSTR)                  // 17408
#define GEMM_SMEM (OFF_B + 128 * GSTR)     // 52224 B

__global__ __launch_bounds__(256, 2)
void gemm_kernel(const float* __restrict__ smb, float* __restrict__ outp)
{
    extern __shared__ char smc[];
    u32 sbse = smem_u32(smc);
    int tid = threadIdx.x;
    int n0 = blockIdx.x * 128;
    int m0 = blockIdx.y * 64;

    for (int idx = tid; idx < 64 * 16; idx += 256) {         // A
        int r = idx >> 4, c = idx & 15;
        int m = m0 + r;
        uint4 v = make_uint4(0, 0, 0, 0);
        if (m < 1568) v = ((const uint4*)g_Ahi)[m * 16 + c];
        *(uint4*)(smc + OFF_A + r * GSTR + c * 16) = v;
    }
    for (int idx = tid; idx < 128 * 16; idx += 256) {        // B
        int r = idx >> 4, c = idx & 15;
        int n = n0 + r;
        *(uint4*)(smc + OFF_B + r * GSTR + c * 16) = ((const uint4*)g_Bhi)[n * 16 + c];
    }
    __syncthreads();

    int wid = tid >> 5, l = tid & 31;
    int wm = (wid >> 2) * 32;
    int wn = (wid & 3) * 32;

    u32 aoff = (u32)((wm + (l & 15)) * GSTR + ((l >> 4) << 4));
    u32 boff = (u32)((wn + ((l >> 4) << 3) + (l & 7)) * GSTR + (((l >> 3) & 1) << 4));
    u32 aAddr = sbse + OFF_A + aoff;
    u32 bAddr = sbse + OFF_B + boff;

    float c[2][4][4];
#pragma unroll
    for (int i = 0; i < 2; i++)
#pragma unroll
        for (int j = 0; j < 4; j++)
#pragma unroll
            for (int q = 0; q < 4; q++) c[i][j][q] = 0.0f;

#pragma unroll
    for (int ks = 0; ks < 8; ks++) {
        u32 a0[4], a1[4], b0[4], b1[4];
        ldsm4(a0, aAddr + ks * 32);
        ldsm4(a1, aAddr + 16 * GSTR + ks * 32);
        ldsm4(b0, bAddr + ks * 32);
        ldsm4(b1, bAddr + 16 * GSTR + ks * 32);
        mma16816(c[0][0], a0, b0[0], b0[1]);
        mma16816(c[0][1], a0, b0[2], b0[3]);
        mma16816(c[0][2], a0, b1[0], b1[1]);
        mma16816(c[0][3], a0, b1[2], b1[3]);
        mma16816(c[1][0], a1, b0[0], b0[1]);
        mma16816(c[1][1], a1, b0[2], b0[3]);
        mma16816(c[1][2], a1, b1[0], b1[1]);
        mma16816(c[1][3], a1, b1[2], b1[3]);
    }

#pragma unroll
    for (int nf = 0; nf < 4; nf++) {
        int cb = n0 + wn + nf * 8 + 2 * (l & 3);
        float2 bv = __ldg((const float2*)(smb + cb));
#pragma unroll
        for (int mf = 0; mf < 2; mf++) {
            int mrow = m0 + wm + mf * 16 + (l >> 2);
#pragma unroll
            for (int h = 0; h < 2; h++) {
                int m = mrow + h * 8;
                if (m < 1568) {
                    int t = m >> 5, b = m & 31;
                    float2 o;
                    o.x = c[mf][nf][h * 2 + 0] + bv.x;
                    o.y = c[mf][nf][h * 2 + 1] + bv.y;
                    *(float2*)(outp + (size_t)(b * 49 + t) * 32000 + cb) = o;
                }
            }
        }
    }
}

extern "C" void kernel_launch(void* const* d_in, const int* in_sizes, int n_in,
                              void* d_out, int out_size)
{
    const int*   src     = (const int*)  d_in[0];
    const int*   trg     = (const int*)  d_in[1];
    const float* emb_src = (const float*)d_in[2];
    const float* emb_trg = (const float*)d_in[3];
    const float* enc_Wih = (const float*)d_in[4];
    const float* enc_Whh = (const float*)d_in[5];
    const float* enc_bih = (const float*)d_in[6];
    const float* enc_bhh = (const float*)d_in[7];
    const float* dec_Wih = (const float*)d_in[8];
    const float* dec_Whh = (const float*)d_in[9];
    const float* dec_bih = (const float*)d_in[10];
    const float* dec_bhh = (const float*)d_in[11];
    const float* att_w1s = (const float*)d_in[12];
    const float* att_b1s = (const float*)d_in[13];
    const float* att_w1t = (const float*)d_in[14];
    const float* att_b1t = (const float*)d_in[15];
    const float* att_w2  = (const float*)d_in[16];
    const float* att_b2  = (const float*)d_in[17];
    const float* out_w   = (const float*)d_in[18];
    const float* out_b   = (const float*)d_in[19];
    const float* sm_w    = (const float*)d_in[20];
    const float* sm_b    = (const float*)d_in[21];
    float* outp = (float*)d_out;

    cudaFuncSetAttribute(lstm_kernel,
                         cudaFuncAttributeMaxDynamicSharedMemorySize, LSTM_SMEM);
    cudaFuncSetAttribute(attn_kernel,
                         cudaFuncAttributeMaxDynamicSharedMemorySize, ATTN_SMEM);
    cudaFuncSetAttribute(gemm_kernel,
                         cudaFuncAttributeMaxDynamicSharedMemorySize, GEMM_SMEM);

    prep_kernel<<<256, 256>>>(att_w1t, out_w, att_w1s);
    pre_kernel<<<396, 256>>>(src, trg, emb_src, emb_trg,
                             enc_Wih, enc_bih, enc_bhh,
                             dec_Wih, dec_bih, dec_bhh);
    convB_kernel<<<1000, 256>>>(sm_w);
    lstm_kernel<<<64, 512, LSTM_SMEM>>>(enc_Whh, dec_Whh, att_b1s);
    attn_kernel<<<dim3(32, 7), 256, ATTN_SMEM>>>(att_b1t, att_w2, att_b2, out_b);
    gemm_kernel<<<dim3(250, 25), 256, GEMM_SMEM>>>(sm_b, outp);
}